// round 1
// baseline (speedup 1.0000x reference)
#include <cuda_runtime.h>
#include <cuda_bf16.h>
#include <math.h>

// Problem constants
#define Bq 2
#define Sq 2048
#define DM 1024
#define Hq 16
#define DHq 64

// ---------------------------------------------------------------------------
// Scratch (sanctioned: __device__ globals, no runtime allocation)
// ---------------------------------------------------------------------------
__device__ float g_qh [(size_t)Bq * Hq * Sq * DHq];   // 16 MB  [B,H,S,DH]
__device__ float g_kh [(size_t)Bq * Hq * Sq * DHq];   // 16 MB  [B,H,S,DH]
__device__ float g_vhT[(size_t)Bq * Hq * DHq * Sq];   // 16 MB  [B,H,DH,S]
__device__ float g_ctx[(size_t)Bq * Sq * DM];          // 16 MB  [B,S,DM]
__device__ float g_attn_scratch[(size_t)Bq * Hq * Sq * Sq]; // 536 MB fallback

// ---------------------------------------------------------------------------
// Generic fp32 GEMM: Y = scale * (X @ W^T) + bias
//   X: [M,K] row-major (per-z base X + z*sXz)
//   W: [N,K] row-major (per-z base W + z*sWz)
// out_mode:
//   0: Y[z*sYz + m*N + n]                        (scores / final out)
//   1: q/k head layout: ((b*H+h)*S+s)*DH+d       (m=b*S+s, n=h*DH+d)
//   2: v transposed:    ((b*H+h)*DH+d)*S+s
//   3: ctx layout:      ((zb*S+m)*DM + zh*DH+n)  (z = zb*H+zh)
// causal_mode: 0 none; 1 skip tile if n0>m0 (scores); 2 K limited to m0+128 (ctx)
// ---------------------------------------------------------------------------
__global__ __launch_bounds__(256)
void gemm_k(const float* __restrict__ X, const float* __restrict__ W,
            const float* __restrict__ bias, float* __restrict__ Y,
            int M, int N, int K,
            long long sXz, long long sWz, long long sYz,
            float scale, int out_mode, int causal_mode)
{
    const int m0 = blockIdx.y * 128;
    const int n0 = blockIdx.x * 128;
    if (causal_mode == 1 && n0 > m0) return;   // fully masked tile

    const int z   = blockIdx.z;
    const int tid = threadIdx.x;

    const float* Xz = X + (long long)z * sXz;
    const float* Wz = W + (long long)z * sWz;

    __shared__ float As[8][128];
    __shared__ float Bs[8][128];

    const int lrow = tid >> 1;        // 0..127
    const int lk   = (tid & 1) * 4;   // 0 or 4

    float acc[8][8];
#pragma unroll
    for (int i = 0; i < 8; i++)
#pragma unroll
        for (int j = 0; j < 8; j++) acc[i][j] = 0.f;

    const int ty = tid >> 4;   // 0..15
    const int tx = tid & 15;   // 0..15

    const int Keff = (causal_mode == 2) ? min(K, m0 + 128) : K;

    for (int k0 = 0; k0 < Keff; k0 += 8) {
        // load X tile (M rows always in-bounds for our shapes)
        float4 xv = *(const float4*)&Xz[(long long)(m0 + lrow) * K + k0 + lk];
        As[lk + 0][lrow] = xv.x;
        As[lk + 1][lrow] = xv.y;
        As[lk + 2][lrow] = xv.z;
        As[lk + 3][lrow] = xv.w;
        // load W tile (guard N: ctx GEMM has N=64)
        float4 wv = make_float4(0.f, 0.f, 0.f, 0.f);
        if (n0 + lrow < N)
            wv = *(const float4*)&Wz[(long long)(n0 + lrow) * K + k0 + lk];
        Bs[lk + 0][lrow] = wv.x;
        Bs[lk + 1][lrow] = wv.y;
        Bs[lk + 2][lrow] = wv.z;
        Bs[lk + 3][lrow] = wv.w;
        __syncthreads();

#pragma unroll
        for (int kk = 0; kk < 8; kk++) {
            float a[8], b[8];
            *(float4*)&a[0] = *(const float4*)&As[kk][ty * 4];
            *(float4*)&a[4] = *(const float4*)&As[kk][64 + ty * 4];
            *(float4*)&b[0] = *(const float4*)&Bs[kk][tx * 4];
            *(float4*)&b[4] = *(const float4*)&Bs[kk][64 + tx * 4];
#pragma unroll
            for (int i = 0; i < 8; i++)
#pragma unroll
                for (int j = 0; j < 8; j++)
                    acc[i][j] += a[i] * b[j];
        }
        __syncthreads();
    }

    // store
#pragma unroll
    for (int i = 0; i < 8; i++) {
        int mi = (i < 4) ? (ty * 4 + i) : (64 + ty * 4 + (i - 4));
        int m  = m0 + mi;
        if (m >= M) continue;
#pragma unroll
        for (int j = 0; j < 8; j++) {
            int ni = (j < 4) ? (tx * 4 + j) : (64 + tx * 4 + (j - 4));
            int n  = n0 + ni;
            if (n >= N) continue;
            float val = acc[i][j] * scale + (bias ? bias[n] : 0.f);
            long long idx;
            if (out_mode == 0) {
                idx = (long long)z * sYz + (long long)m * N + n;
            } else if (out_mode == 1) {
                int b = m >> 11;            // /S
                int s = m & (Sq - 1);
                int h = n >> 6;             // /DH
                int d = n & (DHq - 1);
                idx = (((long long)b * Hq + h) * Sq + s) * DHq + d;
            } else if (out_mode == 2) {
                int b = m >> 11;
                int s = m & (Sq - 1);
                int h = n >> 6;
                int d = n & (DHq - 1);
                idx = (((long long)b * Hq + h) * DHq + d) * Sq + s;
            } else { // 3
                int zb = z >> 4;            // /H
                int zh = z & (Hq - 1);
                idx = ((long long)zb * Sq + m) * DM + zh * DHq + n;
            }
            Y[idx] = val;
        }
    }
}

// ---------------------------------------------------------------------------
// Row softmax with causal mask. One block per row; row cached in smem.
// attn laid out [B*H*S, S]; row r has q = r % S valid entries (k <= q).
// Writes the FULL row (zeros beyond q) since d_out is poisoned.
// ---------------------------------------------------------------------------
__global__ __launch_bounds__(256)
void softmax_k(float* __restrict__ attn)
{
    const int row = blockIdx.x;
    const int q   = row & (Sq - 1);
    float* r = attn + (long long)row * Sq;

    __shared__ float buf[Sq];
    __shared__ float red[8];
    const int tid = threadIdx.x;

    float lmax = -1e30f;
    for (int j = tid; j <= q; j += 256) {
        float v = r[j];
        buf[j] = v;
        lmax = fmaxf(lmax, v);
    }
#pragma unroll
    for (int o = 16; o > 0; o >>= 1)
        lmax = fmaxf(lmax, __shfl_xor_sync(0xffffffffu, lmax, o));
    if ((tid & 31) == 0) red[tid >> 5] = lmax;
    __syncthreads();
    float bmax = red[0];
#pragma unroll
    for (int i = 1; i < 8; i++) bmax = fmaxf(bmax, red[i]);
    __syncthreads();

    float lsum = 0.f;
    for (int j = tid; j <= q; j += 256) {
        float e = __expf(buf[j] - bmax);
        buf[j] = e;
        lsum += e;
    }
#pragma unroll
    for (int o = 16; o > 0; o >>= 1)
        lsum += __shfl_xor_sync(0xffffffffu, lsum, o);
    if ((tid & 31) == 0) red[tid >> 5] = lsum;
    __syncthreads();
    float bsum = 0.f;
#pragma unroll
    for (int i = 0; i < 8; i++) bsum += red[i];
    float inv = 1.0f / bsum;

    for (int j = tid; j < Sq; j += 256)
        r[j] = (j <= q) ? buf[j] * inv : 0.f;
}

// ---------------------------------------------------------------------------
// kernel_launch
// inputs: q,k,v,mask,wq,bq,wk,bk,wv,bv,wo,bo  (mask is the fixed causal tril)
// output: (out [B,S,DM], attn [B,H,S,S]) flattened if out_size covers both
// ---------------------------------------------------------------------------
extern "C" void kernel_launch(void* const* d_in, const int* in_sizes, int n_in,
                              void* d_out, int out_size)
{
    const float* q  = (const float*)d_in[0];
    const float* k  = (const float*)d_in[1];
    const float* v  = (const float*)d_in[2];
    // d_in[3] = mask (causal tril; handled analytically)
    const float* wq = (const float*)d_in[4];
    const float* bq = (const float*)d_in[5];
    const float* wk = (const float*)d_in[6];
    const float* bk = (const float*)d_in[7];
    const float* wv = (const float*)d_in[8];
    const float* bv = (const float*)d_in[9];
    const float* wo = (const float*)d_in[10];
    const float* bo = (const float*)d_in[11];
    float* out = (float*)d_out;

    float *qh, *kh, *vhT, *ctx, *attn_s;
    cudaGetSymbolAddress((void**)&qh,     g_qh);
    cudaGetSymbolAddress((void**)&kh,     g_kh);
    cudaGetSymbolAddress((void**)&vhT,    g_vhT);
    cudaGetSymbolAddress((void**)&ctx,    g_ctx);
    cudaGetSymbolAddress((void**)&attn_s, g_attn_scratch);

    const long long OUT_E  = (long long)Bq * Sq * DM;          // 4,194,304
    const long long ATTN_E = (long long)Bq * Hq * Sq * Sq;     // 134,217,728
    float* attn = ((long long)out_size >= OUT_E + ATTN_E) ? (out + OUT_E) : attn_s;

    dim3 blk(256);

    // 1-3: projections  (M=B*S=4096, N=DM=1024, K=DM=1024)
    dim3 gp(DM / 128, (Bq * Sq) / 128, 1);
    gemm_k<<<gp, blk>>>(q, wq, bq, qh,  Bq * Sq, DM, DM, 0, 0, 0, 1.f, 1, 0);
    gemm_k<<<gp, blk>>>(k, wk, bk, kh,  Bq * Sq, DM, DM, 0, 0, 0, 1.f, 1, 0);
    gemm_k<<<gp, blk>>>(v, wv, bv, vhT, Bq * Sq, DM, DM, 0, 0, 0, 1.f, 2, 0);

    // 4: scores = qh @ kh^T / 8   (per-head, causal tile skip)
    dim3 gs(Sq / 128, Sq / 128, Bq * Hq);
    gemm_k<<<gs, blk>>>(qh, kh, nullptr, attn, Sq, Sq, DHq,
                        (long long)Sq * DHq, (long long)Sq * DHq,
                        (long long)Sq * Sq, 0.125f, 0, 1);

    // 5: causal softmax (writes full attn rows incl. zeros)
    softmax_k<<<Bq * Hq * Sq, blk>>>(attn);

    // 6: ctx = attn @ vh          (K limited causally)
    dim3 gc(1, Sq / 128, Bq * Hq);
    gemm_k<<<gc, blk>>>(attn, vhT, nullptr, ctx, Sq, DHq, Sq,
                        (long long)Sq * Sq, (long long)DHq * Sq,
                        0, 1.f, 3, 2);

    // 7: out = ctx @ wo^T + bo
    gemm_k<<<gp, blk>>>(ctx, wo, bo, out, Bq * Sq, DM, DM, 0, 0, 0, 1.f, 0, 0);
}

// round 2
// speedup vs baseline: 1.0078x; 1.0078x over previous
#include <cuda_runtime.h>
#include <cuda_bf16.h>
#include <math.h>

// Problem constants
#define Bq 2
#define Sq 2048
#define DM 1024
#define Hq 16
#define DHq 64

// ---------------------------------------------------------------------------
// Scratch (sanctioned: __device__ globals, no runtime allocation)
// ---------------------------------------------------------------------------
__device__ float g_qh [(size_t)Bq * Hq * Sq * DHq];   // 16 MB  [B,H,S,DH]
__device__ float g_kh [(size_t)Bq * Hq * Sq * DHq];   // 16 MB  [B,H,S,DH]
__device__ float g_vhT[(size_t)Bq * Hq * DHq * Sq];   // 16 MB  [B,H,DH,S]
__device__ float g_ctx[(size_t)Bq * Sq * DM];          // 16 MB  [B,S,DM]
__device__ float g_attn_scratch[(size_t)Bq * Hq * Sq * Sq]; // 536 MB fallback

// ---------------------------------------------------------------------------
// Generic fp32 GEMM: Y = scale * (X @ W^T) + bias
//   X: [M,K] row-major (per-z base X + z*sXz)
//   W: [N,K] row-major (per-z base W + z*sWz)
// out_mode:
//   0: Y[z*sYz + m*N + n]                        (scores / final out)
//   1: q/k head layout: ((b*H+h)*S+s)*DH+d       (m=b*S+s, n=h*DH+d)
//   2: v transposed:    ((b*H+h)*DH+d)*S+s
//   3: ctx layout:      ((zb*S+m)*DM + zh*DH+n)  (z = zb*H+zh)
// causal_mode: 0 none; 1 skip tile if n0>m0 (scores); 2 K limited to m0+128 (ctx)
// ---------------------------------------------------------------------------
__global__ __launch_bounds__(256)
void gemm_k(const float* __restrict__ X, const float* __restrict__ W,
            const float* __restrict__ bias, float* __restrict__ Y,
            int M, int N, int K,
            long long sXz, long long sWz, long long sYz,
            float scale, int out_mode, int causal_mode)
{
    const int m0 = blockIdx.y * 128;
    const int n0 = blockIdx.x * 128;
    if (causal_mode == 1 && n0 > m0) return;   // fully masked tile

    const int z   = blockIdx.z;
    const int tid = threadIdx.x;

    const float* Xz = X + (long long)z * sXz;
    const float* Wz = W + (long long)z * sWz;

    __shared__ float As[8][128];
    __shared__ float Bs[8][128];

    const int lrow = tid >> 1;        // 0..127
    const int lk   = (tid & 1) * 4;   // 0 or 4

    float acc[8][8];
#pragma unroll
    for (int i = 0; i < 8; i++)
#pragma unroll
        for (int j = 0; j < 8; j++) acc[i][j] = 0.f;

    const int ty = tid >> 4;   // 0..15
    const int tx = tid & 15;   // 0..15

    const int Keff = (causal_mode == 2) ? min(K, m0 + 128) : K;

    for (int k0 = 0; k0 < Keff; k0 += 8) {
        // load X tile (M rows always in-bounds for our shapes)
        float4 xv = *(const float4*)&Xz[(long long)(m0 + lrow) * K + k0 + lk];
        As[lk + 0][lrow] = xv.x;
        As[lk + 1][lrow] = xv.y;
        As[lk + 2][lrow] = xv.z;
        As[lk + 3][lrow] = xv.w;
        // load W tile (guard N: ctx GEMM has N=64)
        float4 wv = make_float4(0.f, 0.f, 0.f, 0.f);
        if (n0 + lrow < N)
            wv = *(const float4*)&Wz[(long long)(n0 + lrow) * K + k0 + lk];
        Bs[lk + 0][lrow] = wv.x;
        Bs[lk + 1][lrow] = wv.y;
        Bs[lk + 2][lrow] = wv.z;
        Bs[lk + 3][lrow] = wv.w;
        __syncthreads();

#pragma unroll
        for (int kk = 0; kk < 8; kk++) {
            float a[8], b[8];
            *(float4*)&a[0] = *(const float4*)&As[kk][ty * 4];
            *(float4*)&a[4] = *(const float4*)&As[kk][64 + ty * 4];
            *(float4*)&b[0] = *(const float4*)&Bs[kk][tx * 4];
            *(float4*)&b[4] = *(const float4*)&Bs[kk][64 + tx * 4];
#pragma unroll
            for (int i = 0; i < 8; i++)
#pragma unroll
                for (int j = 0; j < 8; j++)
                    acc[i][j] += a[i] * b[j];
        }
        __syncthreads();
    }

    // store
#pragma unroll
    for (int i = 0; i < 8; i++) {
        int mi = (i < 4) ? (ty * 4 + i) : (64 + ty * 4 + (i - 4));
        int m  = m0 + mi;
        if (m >= M) continue;
#pragma unroll
        for (int j = 0; j < 8; j++) {
            int ni = (j < 4) ? (tx * 4 + j) : (64 + tx * 4 + (j - 4));
            int n  = n0 + ni;
            if (n >= N) continue;
            float val = acc[i][j] * scale + (bias ? bias[n] : 0.f);
            long long idx;
            if (out_mode == 0) {
                idx = (long long)z * sYz + (long long)m * N + n;
            } else if (out_mode == 1) {
                int b = m >> 11;            // /S
                int s = m & (Sq - 1);
                int h = n >> 6;             // /DH
                int d = n & (DHq - 1);
                idx = (((long long)b * Hq + h) * Sq + s) * DHq + d;
            } else if (out_mode == 2) {
                int b = m >> 11;
                int s = m & (Sq - 1);
                int h = n >> 6;
                int d = n & (DHq - 1);
                idx = (((long long)b * Hq + h) * DHq + d) * Sq + s;
            } else { // 3
                int zb = z >> 4;            // /H
                int zh = z & (Hq - 1);
                idx = ((long long)zb * Sq + m) * DM + zh * DHq + n;
            }
            Y[idx] = val;
        }
    }
}

// ---------------------------------------------------------------------------
// Row softmax with causal mask. One block per row; row cached in smem.
// attn laid out [B*H*S, S]; row r has q = r % S valid entries (k <= q).
// Writes the FULL row (zeros beyond q) since d_out is poisoned.
// ---------------------------------------------------------------------------
__global__ __launch_bounds__(256)
void softmax_k(float* __restrict__ attn)
{
    const int row = blockIdx.x;
    const int q   = row & (Sq - 1);
    float* r = attn + (long long)row * Sq;

    __shared__ float buf[Sq];
    __shared__ float red[8];
    const int tid = threadIdx.x;

    float lmax = -1e30f;
    for (int j = tid; j <= q; j += 256) {
        float v = r[j];
        buf[j] = v;
        lmax = fmaxf(lmax, v);
    }
#pragma unroll
    for (int o = 16; o > 0; o >>= 1)
        lmax = fmaxf(lmax, __shfl_xor_sync(0xffffffffu, lmax, o));
    if ((tid & 31) == 0) red[tid >> 5] = lmax;
    __syncthreads();
    float bmax = red[0];
#pragma unroll
    for (int i = 1; i < 8; i++) bmax = fmaxf(bmax, red[i]);
    __syncthreads();

    float lsum = 0.f;
    for (int j = tid; j <= q; j += 256) {
        float e = __expf(buf[j] - bmax);
        buf[j] = e;
        lsum += e;
    }
#pragma unroll
    for (int o = 16; o > 0; o >>= 1)
        lsum += __shfl_xor_sync(0xffffffffu, lsum, o);
    if ((tid & 31) == 0) red[tid >> 5] = lsum;
    __syncthreads();
    float bsum = 0.f;
#pragma unroll
    for (int i = 0; i < 8; i++) bsum += red[i];
    float inv = 1.0f / bsum;

    for (int j = tid; j < Sq; j += 256)
        r[j] = (j <= q) ? buf[j] * inv : 0.f;
}

// ---------------------------------------------------------------------------
// kernel_launch
// inputs: q,k,v,mask,wq,bq,wk,bk,wv,bv,wo,bo  (mask is the fixed causal tril)
// output: (out [B,S,DM], attn [B,H,S,S]) flattened if out_size covers both
// ---------------------------------------------------------------------------
extern "C" void kernel_launch(void* const* d_in, const int* in_sizes, int n_in,
                              void* d_out, int out_size)
{
    const float* q  = (const float*)d_in[0];
    const float* k  = (const float*)d_in[1];
    const float* v  = (const float*)d_in[2];
    // d_in[3] = mask (causal tril; handled analytically)
    const float* wq = (const float*)d_in[4];
    const float* bq = (const float*)d_in[5];
    const float* wk = (const float*)d_in[6];
    const float* bk = (const float*)d_in[7];
    const float* wv = (const float*)d_in[8];
    const float* bv = (const float*)d_in[9];
    const float* wo = (const float*)d_in[10];
    const float* bo = (const float*)d_in[11];
    float* out = (float*)d_out;

    float *qh, *kh, *vhT, *ctx, *attn_s;
    cudaGetSymbolAddress((void**)&qh,     g_qh);
    cudaGetSymbolAddress((void**)&kh,     g_kh);
    cudaGetSymbolAddress((void**)&vhT,    g_vhT);
    cudaGetSymbolAddress((void**)&ctx,    g_ctx);
    cudaGetSymbolAddress((void**)&attn_s, g_attn_scratch);

    const long long OUT_E  = (long long)Bq * Sq * DM;          // 4,194,304
    const long long ATTN_E = (long long)Bq * Hq * Sq * Sq;     // 134,217,728
    float* attn = ((long long)out_size >= OUT_E + ATTN_E) ? (out + OUT_E) : attn_s;

    dim3 blk(256);

    // 1-3: projections  (M=B*S=4096, N=DM=1024, K=DM=1024)
    dim3 gp(DM / 128, (Bq * Sq) / 128, 1);
    gemm_k<<<gp, blk>>>(q, wq, bq, qh,  Bq * Sq, DM, DM, 0, 0, 0, 1.f, 1, 0);
    gemm_k<<<gp, blk>>>(k, wk, bk, kh,  Bq * Sq, DM, DM, 0, 0, 0, 1.f, 1, 0);
    gemm_k<<<gp, blk>>>(v, wv, bv, vhT, Bq * Sq, DM, DM, 0, 0, 0, 1.f, 2, 0);

    // 4: scores = qh @ kh^T / 8   (per-head, causal tile skip)
    dim3 gs(Sq / 128, Sq / 128, Bq * Hq);
    gemm_k<<<gs, blk>>>(qh, kh, nullptr, attn, Sq, Sq, DHq,
                        (long long)Sq * DHq, (long long)Sq * DHq,
                        (long long)Sq * Sq, 0.125f, 0, 1);

    // 5: causal softmax (writes full attn rows incl. zeros)
    softmax_k<<<Bq * Hq * Sq, blk>>>(attn);

    // 6: ctx = attn @ vh          (K limited causally)
    dim3 gc(1, Sq / 128, Bq * Hq);
    gemm_k<<<gc, blk>>>(attn, vhT, nullptr, ctx, Sq, DHq, Sq,
                        (long long)Sq * Sq, (long long)DHq * Sq,
                        0, 1.f, 3, 2);

    // 7: out = ctx @ wo^T + bo
    gemm_k<<<gp, blk>>>(ctx, wo, bo, out, Bq * Sq, DM, DM, 0, 0, 0, 1.f, 0, 0);
}

// round 3
// speedup vs baseline: 2.2921x; 2.2744x over previous
#include <cuda_runtime.h>
#include <cuda_bf16.h>
#include <math.h>

// Problem constants
#define Bq 2
#define Sq 2048
#define DM 1024
#define Hq 16
#define DHq 64

// ---------------------------------------------------------------------------
// Scratch (__device__ globals; no runtime allocation)
// ---------------------------------------------------------------------------
__device__ float g_qh [(size_t)Bq * Hq * Sq * DHq];   // [B,H,S,DH]
__device__ float g_kh [(size_t)Bq * Hq * Sq * DHq];   // [B,H,S,DH]
__device__ float g_vh [(size_t)Bq * Hq * Sq * DHq];   // [B,H,S,DH]  (row-major, used as W in ctx GEMM)
__device__ float g_ctx[(size_t)Bq * Sq * DM];          // [B,S,DM]
__device__ float g_attn_scratch[(size_t)Bq * Hq * Sq * Sq]; // fallback if attn not in d_out

// ---------------------------------------------------------------------------
// TF32 tensor-core GEMM: Y = scale * (X @ W^T) + bias
//   X: [M,K] row-major (per-z base X + z*sXz)
//   W: [N,K] row-major (per-z base W + z*sWz)
// Block tile 128x128, Kstep 32, 8 warps (2 M x 4 N), mma.m16n8k8.tf32.
// out_mode:
//   0: Y[z*sYz + m*N + n]
//   1: head layout ((b*H+h)*S+s)*DH+d      (m=b*S+s, n=h*DH+d)
//   3: ctx layout  ((zb*S+m)*DM + zh*DH+n) (z = zb*H+zh)
// causal_mode: 0 none; 1 skip tile if n0>m0; 2 Keff = min(K, m0+128)
// ---------------------------------------------------------------------------

__device__ __forceinline__ unsigned f2tf32(float f) {
    unsigned r;
    asm("cvt.rna.tf32.f32 %0, %1;" : "=r"(r) : "f"(f));
    return r;
}

#define SM_STRIDE 36   // 32 + 4 pad words: makes frag loads & STS.128 conflict-free

__global__ __launch_bounds__(256)
void gemm_tc(const float* __restrict__ X, const float* __restrict__ W,
             const float* __restrict__ bias, float* __restrict__ Y,
             int M, int N, int K,
             long long sXz, long long sWz, long long sYz,
             float scale, int out_mode, int causal_mode)
{
    const int m0 = blockIdx.y * 128;
    const int n0 = blockIdx.x * 128;
    if (causal_mode == 1 && n0 > m0) return;

    const int z    = blockIdx.z;
    const int tid  = threadIdx.x;
    const int lane = tid & 31;
    const int warp = tid >> 5;
    const int wm   = warp & 1;    // 0..1  (64-row slab)
    const int wn   = warp >> 1;   // 0..3  (32-col slab)

    const float* Xz = X + (long long)z * sXz;
    const float* Wz = W + (long long)z * sWz;

    __shared__ unsigned As[128][SM_STRIDE];  // tf32 bits, [m][k]
    __shared__ unsigned Bs[128][SM_STRIDE];  // tf32 bits, [n][k]

    float acc[4][4][4];
#pragma unroll
    for (int i = 0; i < 4; i++)
#pragma unroll
        for (int j = 0; j < 4; j++)
#pragma unroll
            for (int e = 0; e < 4; e++) acc[i][j][e] = 0.f;

    const int Keff = (causal_mode == 2) ? min(K, m0 + 128) : K;

    // global-load coords: 4 float4 per thread per tile
    const int grow = tid >> 3;        // 0..31  (+32 per it)
    const int gc4  = tid & 7;         // 0..7   -> k offset gc4*4

    for (int k0 = 0; k0 < Keff; k0 += 32) {
        // ---- load A tile 128x32 ----
#pragma unroll
        for (int it = 0; it < 4; it++) {
            int r = grow + it * 32;
            float4 xv = *(const float4*)&Xz[(long long)(m0 + r) * K + k0 + gc4 * 4];
            unsigned* dst = &As[r][gc4 * 4];
            dst[0] = f2tf32(xv.x); dst[1] = f2tf32(xv.y);
            dst[2] = f2tf32(xv.z); dst[3] = f2tf32(xv.w);
        }
        // ---- load B tile 128x32 (guard N) ----
#pragma unroll
        for (int it = 0; it < 4; it++) {
            int r = grow + it * 32;
            float4 wv = make_float4(0.f, 0.f, 0.f, 0.f);
            if (n0 + r < N)
                wv = *(const float4*)&Wz[(long long)(n0 + r) * K + k0 + gc4 * 4];
            unsigned* dst = &Bs[r][gc4 * 4];
            dst[0] = f2tf32(wv.x); dst[1] = f2tf32(wv.y);
            dst[2] = f2tf32(wv.z); dst[3] = f2tf32(wv.w);
        }
        __syncthreads();

#pragma unroll
        for (int kk = 0; kk < 32; kk += 8) {
            // A frags: 4 m-tiles x 4 regs
            unsigned a[4][4];
#pragma unroll
            for (int i = 0; i < 4; i++) {
                int mr = wm * 64 + i * 16 + (lane >> 2);
                int kc = kk + (lane & 3);
                a[i][0] = As[mr    ][kc    ];
                a[i][1] = As[mr + 8][kc    ];
                a[i][2] = As[mr    ][kc + 4];
                a[i][3] = As[mr + 8][kc + 4];
            }
            // B frags: 4 n-tiles x 2 regs
            unsigned b[4][2];
#pragma unroll
            for (int j = 0; j < 4; j++) {
                int nr = wn * 32 + j * 8 + (lane >> 2);
                int kc = kk + (lane & 3);
                b[j][0] = Bs[nr][kc    ];
                b[j][1] = Bs[nr][kc + 4];
            }
#pragma unroll
            for (int i = 0; i < 4; i++)
#pragma unroll
                for (int j = 0; j < 4; j++) {
                    asm volatile(
                        "mma.sync.aligned.m16n8k8.row.col.f32.tf32.tf32.f32 "
                        "{%0,%1,%2,%3}, {%4,%5,%6,%7}, {%8,%9}, {%0,%1,%2,%3};"
                        : "+f"(acc[i][j][0]), "+f"(acc[i][j][1]),
                          "+f"(acc[i][j][2]), "+f"(acc[i][j][3])
                        : "r"(a[i][0]), "r"(a[i][1]), "r"(a[i][2]), "r"(a[i][3]),
                          "r"(b[j][0]), "r"(b[j][1]));
                }
        }
        __syncthreads();
    }

    // ---- store ----
#pragma unroll
    for (int i = 0; i < 4; i++) {
#pragma unroll
        for (int j = 0; j < 4; j++) {
#pragma unroll
            for (int e = 0; e < 4; e++) {
                int m = m0 + wm * 64 + i * 16 + (lane >> 2) + ((e >= 2) ? 8 : 0);
                int n = n0 + wn * 32 + j * 8 + (lane & 3) * 2 + (e & 1);
                if (n >= N || m >= M) continue;
                float val = acc[i][j][e] * scale + (bias ? bias[n] : 0.f);
                long long idx;
                if (out_mode == 0) {
                    idx = (long long)z * sYz + (long long)m * N + n;
                } else if (out_mode == 1) {
                    int b_ = m >> 11;           // /S
                    int s  = m & (Sq - 1);
                    int h  = n >> 6;            // /DH
                    int d  = n & (DHq - 1);
                    idx = (((long long)b_ * Hq + h) * Sq + s) * DHq + d;
                } else { // 3
                    int zb = z >> 4;
                    int zh = z & (Hq - 1);
                    idx = ((long long)zb * Sq + m) * DM + zh * DHq + n;
                }
                Y[idx] = val;
            }
        }
    }
}

// ---------------------------------------------------------------------------
// Row softmax with causal mask. One block per row; row cached in smem.
// ---------------------------------------------------------------------------
__global__ __launch_bounds__(256)
void softmax_k(float* __restrict__ attn)
{
    const int row = blockIdx.x;
    const int q   = row & (Sq - 1);
    float* r = attn + (long long)row * Sq;

    __shared__ float buf[Sq];
    __shared__ float red[8];
    const int tid = threadIdx.x;

    float lmax = -1e30f;
    for (int j = tid; j <= q; j += 256) {
        float v = r[j];
        buf[j] = v;
        lmax = fmaxf(lmax, v);
    }
#pragma unroll
    for (int o = 16; o > 0; o >>= 1)
        lmax = fmaxf(lmax, __shfl_xor_sync(0xffffffffu, lmax, o));
    if ((tid & 31) == 0) red[tid >> 5] = lmax;
    __syncthreads();
    float bmax = red[0];
#pragma unroll
    for (int i = 1; i < 8; i++) bmax = fmaxf(bmax, red[i]);
    __syncthreads();

    float lsum = 0.f;
    for (int j = tid; j <= q; j += 256) {
        float e = __expf(buf[j] - bmax);
        buf[j] = e;
        lsum += e;
    }
#pragma unroll
    for (int o = 16; o > 0; o >>= 1)
        lsum += __shfl_xor_sync(0xffffffffu, lsum, o);
    if ((tid & 31) == 0) red[tid >> 5] = lsum;
    __syncthreads();
    float bsum = 0.f;
#pragma unroll
    for (int i = 0; i < 8; i++) bsum += red[i];
    float inv = 1.0f / bsum;

    for (int j = tid; j < Sq; j += 256)
        r[j] = (j <= q) ? buf[j] * inv : 0.f;
}

// ---------------------------------------------------------------------------
// kernel_launch
// ---------------------------------------------------------------------------
extern "C" void kernel_launch(void* const* d_in, const int* in_sizes, int n_in,
                              void* d_out, int out_size)
{
    const float* q  = (const float*)d_in[0];
    const float* k  = (const float*)d_in[1];
    const float* v  = (const float*)d_in[2];
    // d_in[3] = mask (causal tril; handled analytically)
    const float* wq = (const float*)d_in[4];
    const float* bq = (const float*)d_in[5];
    const float* wk = (const float*)d_in[6];
    const float* bk = (const float*)d_in[7];
    const float* wv = (const float*)d_in[8];
    const float* bv = (const float*)d_in[9];
    const float* wo = (const float*)d_in[10];
    const float* bo = (const float*)d_in[11];
    float* out = (float*)d_out;

    float *qh, *kh, *vh, *ctx, *attn_s;
    cudaGetSymbolAddress((void**)&qh,     g_qh);
    cudaGetSymbolAddress((void**)&kh,     g_kh);
    cudaGetSymbolAddress((void**)&vh,     g_vh);
    cudaGetSymbolAddress((void**)&ctx,    g_ctx);
    cudaGetSymbolAddress((void**)&attn_s, g_attn_scratch);

    const long long OUT_E  = (long long)Bq * Sq * DM;
    const long long ATTN_E = (long long)Bq * Hq * Sq * Sq;
    float* attn = ((long long)out_size >= OUT_E + ATTN_E) ? (out + OUT_E) : attn_s;

    dim3 blk(256);

    // projections (M=4096, N=1024, K=1024) -> head layouts
    dim3 gp(DM / 128, (Bq * Sq) / 128, 1);
    gemm_tc<<<gp, blk>>>(q, wq, bq, qh, Bq * Sq, DM, DM, 0, 0, 0, 1.f, 1, 0);
    gemm_tc<<<gp, blk>>>(k, wk, bk, kh, Bq * Sq, DM, DM, 0, 0, 0, 1.f, 1, 0);
    gemm_tc<<<gp, blk>>>(v, wv, bv, vh, Bq * Sq, DM, DM, 0, 0, 0, 1.f, 1, 0);

    // scores = qh @ kh^T / 8  (per-head, causal tile skip)
    dim3 gs(Sq / 128, Sq / 128, Bq * Hq);
    gemm_tc<<<gs, blk>>>(qh, kh, nullptr, attn, Sq, Sq, DHq,
                         (long long)Sq * DHq, (long long)Sq * DHq,
                         (long long)Sq * Sq, 0.125f, 0, 1);

    // causal softmax
    softmax_k<<<Bq * Hq * Sq, blk>>>(attn);

    // ctx = attn @ vh^T ... vh rows are [s][d]; we need ctx[m][d] = sum_k attn[m][k]*vh[k][d]
    // => W = vh^T? gemm computes X @ W^T with W:[N,K]: W[d][k] = vh[k][d]. vh is [S,DH] row-major,
    // i.e. W^T already = vh. Use vh as [K=S rows][DH] -> need W[N=DH][K=S]: that's vh transposed.
    // Trick: gemm_tc reads W rows along K; pass vh with "N" rows of length K laid out as
    // vhT. To avoid a transpose kernel, note DH=64: treat W[n][k] = vh[k][n] is NOT row-major.
    // Instead run with X=attn [S,S], W=vhT. We build vhT implicitly by using the scores-style
    // GEMM with A=vh? Simpler: keep a transpose: ctx GEMM needs vhT [DH,S]. Do it with a tiny
    // dedicated pass below (cheap: 16MB). -- see transpose_k
    {
        static_assert(DHq == 64, "");
    }
    // transpose vh [z][S][DH] -> reuse g_qh is still needed? qh free after scores? No: attn uses qh
    // only in scores (done). Reuse qh buffer as vhT.
    float* vhT = qh; // safe: qh consumed by scores GEMM which completed before this launch
    {
        extern __global__ void transpose_k(const float*, float*);
        transpose_k<<<dim3(Sq / 32, DHq / 32, Bq * Hq), dim3(32, 8)>>>(vh, vhT);
    }
    dim3 gc(1, Sq / 128, Bq * Hq);
    gemm_tc<<<gc, blk>>>(attn, vhT, nullptr, ctx, Sq, DHq, Sq,
                         (long long)Sq * Sq, (long long)DHq * Sq,
                         0, 1.f, 3, 2);

    // out = ctx @ wo^T + bo
    gemm_tc<<<gp, blk>>>(ctx, wo, bo, out, Bq * Sq, DM, DM, 0, 0, 0, 1.f, 0, 0);
}

// per-head transpose: in [z][S][DH] -> out [z][DH][S]
__global__ void transpose_k(const float* __restrict__ in, float* __restrict__ out)
{
    __shared__ float t[32][33];
    const int z  = blockIdx.z;
    const int s0 = blockIdx.x * 32;
    const int d0 = blockIdx.y * 32;
    const float* inz  = in  + (long long)z * Sq * DHq;
    float*       outz = out + (long long)z * DHq * Sq;

    for (int r = threadIdx.y; r < 32; r += 8)
        t[r][threadIdx.x] = inz[(long long)(s0 + r) * DHq + d0 + threadIdx.x];
    __syncthreads();
    for (int r = threadIdx.y; r < 32; r += 8)
        outz[(long long)(d0 + r) * Sq + s0 + threadIdx.x] = t[threadIdx.x][r];
}

// round 4
// speedup vs baseline: 2.4271x; 1.0589x over previous
#include <cuda_runtime.h>
#include <math.h>

// Problem constants
#define Bq 2
#define Sq 2048
#define DM 1024
#define Hq 16
#define DHq 64

// ---------------------------------------------------------------------------
// Scratch (__device__ globals; zero-initialized at load, no runtime alloc)
// ---------------------------------------------------------------------------
__device__ float g_qh [(size_t)Bq * Hq * Sq * DHq];          // [B,H,S,DH]
__device__ float g_kh [(size_t)Bq * Hq * Sq * DHq];          // [B,H,S,DH]
__device__ float g_vh [(size_t)Bq * Hq * Sq * DHq + 128];    // [B,H,S,DH] (+pad for wrow overread)
__device__ float g_ctx[(size_t)Bq * Sq * DM];                 // [B,S,DM]
__device__ float g_attn_scratch[(size_t)Bq * Hq * Sq * Sq];   // fallback if attn not in d_out

// ---------------------------------------------------------------------------
// GEMM params
// ---------------------------------------------------------------------------
struct GemmP {
    const float *X, *W, *bias; float *Y;           // z==0 (or non-qkv) operand set
    const float *X1, *W1, *b1; float *Y1;          // z==1 (qkv)
    const float *X2, *W2, *b2; float *Y2;          // z==2 (qkv)
    int M, N, K, ldw;                               // ldw: W row stride when wrow=1
    long long sXz, sWz, sYz;
    float scale;
    int out_mode;     // 0: z*sYz+m*N+n ; 1: head layout ; 3: ctx layout
    int causal_mode;  // 0 none; 1 zero-fill tile if n0>m0; 2 Keff=min(K,m0+128)
    int wrow;         // 0: W is [N,K]; 1: W is [K,N] row-major (stride ldw)
    int qkv;          // 1: z selects among 3 operand sets
};

#define AS   36          // smem row stride (words) for [128][32] tiles
#define BS2  132         // smem row stride (words) for [32][128] k-major tiles
#define A_WORDS 4608     // 128*36
#define SMEM_WORDS (4 * A_WORDS)
#define SMEM_BYTES (SMEM_WORDS * 4)

__device__ __forceinline__ unsigned f2tf32(float f) {
    unsigned r; asm("cvt.rna.tf32.f32 %0, %1;" : "=r"(r) : "f"(f)); return r;
}
__device__ __forceinline__ void cpa16(float* dst, const float* src) {
    unsigned d = (unsigned)__cvta_generic_to_shared(dst);
    asm volatile("cp.async.cg.shared.global [%0], [%1], 16;" :: "r"(d), "l"(src));
}
__device__ __forceinline__ void cp_commit() { asm volatile("cp.async.commit_group;"); }
__device__ __forceinline__ void cp_wait1()  { asm volatile("cp.async.wait_group 1;"); }

// ---------------------------------------------------------------------------
// TF32 tensor-core GEMM, 128x128 tile, Kstep 32, cp.async double-buffered.
// 8 warps: 2 (M) x 4 (N); each warp 64x32 via 16x m16n8k8 per k8-step.
// ---------------------------------------------------------------------------
__global__ __launch_bounds__(256)
void gemm_tc(GemmP p)
{
    const int m0 = blockIdx.y * 128;
    const int n0 = blockIdx.x * 128;
    const int z  = blockIdx.z;
    const int tid = threadIdx.x, lane = tid & 31, warp = tid >> 5;
    const int wm = warp & 1, wn = warp >> 1;

    const float *X = p.X, *W = p.W, *bias = p.bias; float* Y = p.Y;
    if (p.qkv) {
        if (z == 1) { X = p.X1; W = p.W1; bias = p.b1; Y = p.Y1; }
        else if (z == 2) { X = p.X2; W = p.W2; bias = p.b2; Y = p.Y2; }
    }
    const float* Xz = X + (p.qkv ? 0 : (long long)z * p.sXz);
    const float* Wz = W + (p.qkv ? 0 : (long long)z * p.sWz);

    // Causally skipped tile: zero-fill output (softmax then never touches it)
    if (p.causal_mode == 1 && n0 > m0) {
        float4 z4 = make_float4(0.f, 0.f, 0.f, 0.f);
        float* Yz = Y + (long long)z * p.sYz;
        for (int i = tid; i < 128 * 32; i += 256) {
            int r = i >> 5, c = (i & 31) * 4;
            *(float4*)&Yz[(long long)(m0 + r) * p.N + n0 + c] = z4;
        }
        return;
    }

    extern __shared__ float sm[];
    float* Abuf[2] = { sm,               sm + A_WORDS     };
    float* Bbuf[2] = { sm + 2 * A_WORDS, sm + 3 * A_WORDS };

    const int Keff = (p.causal_mode == 2) ? min(p.K, m0 + 128) : p.K;

    // loaders: 4x cp.async(16B) each per thread per tile
    auto loadA = [&](float* As, int k0) {
        int r0 = tid >> 3, c = (tid & 7) * 4;
#pragma unroll
        for (int it = 0; it < 4; it++) {
            int r = r0 + it * 32;
            cpa16(&As[r * AS + c], &Xz[(long long)(m0 + r) * p.K + k0 + c]);
        }
    };
    auto loadB = [&](float* Bs, int k0) {
        if (!p.wrow) {  // W [N,K], N%128==0 for all wrow=0 uses
            int r0 = tid >> 3, c = (tid & 7) * 4;
#pragma unroll
            for (int it = 0; it < 4; it++) {
                int r = r0 + it * 32;
                cpa16(&Bs[r * AS + c], &Wz[(long long)(n0 + r) * p.K + k0 + c]);
            }
        } else {        // W [K,N] row-major, stride ldw (overread cols ok, buffer padded)
            int kr = tid >> 3, c0 = (tid & 7) * 4;
#pragma unroll
            for (int it = 0; it < 4; it++) {
                int c = c0 + it * 32;
                cpa16(&Bs[kr * BS2 + c], &Wz[(long long)(k0 + kr) * p.ldw + n0 + c]);
            }
        }
    };

    float acc[4][4][4] = {};

    loadA(Abuf[0], 0); loadB(Bbuf[0], 0); cp_commit();
    int st = 0;
    for (int k0 = 0; k0 < Keff; k0 += 32) {
        if (k0 + 32 < Keff) { loadA(Abuf[st ^ 1], k0 + 32); loadB(Bbuf[st ^ 1], k0 + 32); }
        cp_commit();
        cp_wait1();
        __syncthreads();

        const float* As = Abuf[st];
        const float* Bs = Bbuf[st];
#pragma unroll
        for (int kk = 0; kk < 32; kk += 8) {
            unsigned a[4][4];
#pragma unroll
            for (int i = 0; i < 4; i++) {
                int mr = wm * 64 + i * 16 + (lane >> 2);
                int kc = kk + (lane & 3);
                a[i][0] = f2tf32(As[mr * AS + kc]);
                a[i][1] = f2tf32(As[(mr + 8) * AS + kc]);
                a[i][2] = f2tf32(As[mr * AS + kc + 4]);
                a[i][3] = f2tf32(As[(mr + 8) * AS + kc + 4]);
            }
            unsigned b[4][2];
#pragma unroll
            for (int j = 0; j < 4; j++) {
                int nr = wn * 32 + j * 8 + (lane >> 2);
                int kc = kk + (lane & 3);
                if (!p.wrow) {
                    b[j][0] = f2tf32(Bs[nr * AS + kc]);
                    b[j][1] = f2tf32(Bs[nr * AS + kc + 4]);
                } else {
                    b[j][0] = f2tf32(Bs[kc * BS2 + nr]);
                    b[j][1] = f2tf32(Bs[(kc + 4) * BS2 + nr]);
                }
            }
#pragma unroll
            for (int i = 0; i < 4; i++)
#pragma unroll
                for (int j = 0; j < 4; j++) {
                    asm volatile(
                        "mma.sync.aligned.m16n8k8.row.col.f32.tf32.tf32.f32 "
                        "{%0,%1,%2,%3}, {%4,%5,%6,%7}, {%8,%9}, {%0,%1,%2,%3};"
                        : "+f"(acc[i][j][0]), "+f"(acc[i][j][1]),
                          "+f"(acc[i][j][2]), "+f"(acc[i][j][3])
                        : "r"(a[i][0]), "r"(a[i][1]), "r"(a[i][2]), "r"(a[i][3]),
                          "r"(b[j][0]), "r"(b[j][1]));
                }
        }
        __syncthreads();
        st ^= 1;
    }

    // epilogue: float2 stores (n even pairs)
#pragma unroll
    for (int i = 0; i < 4; i++) {
#pragma unroll
        for (int j = 0; j < 4; j++) {
#pragma unroll
            for (int h = 0; h < 2; h++) {
                int m = m0 + wm * 64 + i * 16 + (lane >> 2) + h * 8;
                int n = n0 + wn * 32 + j * 8 + (lane & 3) * 2;
                if (n >= p.N) continue;
                float v0 = acc[i][j][h * 2]     * p.scale;
                float v1 = acc[i][j][h * 2 + 1] * p.scale;
                if (bias) { v0 += bias[n]; v1 += bias[n + 1]; }
                long long idx;
                if (p.out_mode == 0) {
                    idx = (long long)z * p.sYz + (long long)m * p.N + n;
                } else if (p.out_mode == 1) {
                    int b_ = m >> 11;          // /S
                    int s  = m & (Sq - 1);
                    int hh = n >> 6;           // /DH
                    int d  = n & (DHq - 1);
                    idx = (((long long)b_ * Hq + hh) * Sq + s) * DHq + d;
                } else { // 3
                    int zb = z >> 4;
                    int zh = z & (Hq - 1);
                    idx = ((long long)zb * Sq + m) * DM + zh * DHq + n;
                }
                *(float2*)&Y[idx] = make_float2(v0, v1);
            }
        }
    }
}

// ---------------------------------------------------------------------------
// Causal row softmax. One block per row; only touches j < roundup128(q+1)
// (entries beyond were zero-filled by the scores GEMM's skipped tiles).
// ---------------------------------------------------------------------------
__global__ __launch_bounds__(256)
void softmax_k(float* __restrict__ attn)
{
    const int row  = blockIdx.x;
    const int q    = row & (Sq - 1);
    const int qEnd = min(Sq, ((q >> 7) + 1) << 7);
    float* r = attn + (long long)row * Sq;

    __shared__ float buf[Sq];
    __shared__ float red[8];
    const int tid = threadIdx.x;

    float lmax = -1e30f;
    for (int j = tid; j <= q; j += 256) {
        float v = r[j];
        buf[j] = v;
        lmax = fmaxf(lmax, v);
    }
#pragma unroll
    for (int o = 16; o > 0; o >>= 1)
        lmax = fmaxf(lmax, __shfl_xor_sync(0xffffffffu, lmax, o));
    if ((tid & 31) == 0) red[tid >> 5] = lmax;
    __syncthreads();
    float bmax = red[0];
#pragma unroll
    for (int i = 1; i < 8; i++) bmax = fmaxf(bmax, red[i]);
    __syncthreads();

    float lsum = 0.f;
    for (int j = tid; j <= q; j += 256) {
        float e = __expf(buf[j] - bmax);
        buf[j] = e;
        lsum += e;
    }
#pragma unroll
    for (int o = 16; o > 0; o >>= 1)
        lsum += __shfl_xor_sync(0xffffffffu, lsum, o);
    if ((tid & 31) == 0) red[tid >> 5] = lsum;
    __syncthreads();
    float bsum = 0.f;
#pragma unroll
    for (int i = 0; i < 8; i++) bsum += red[i];
    float inv = 1.0f / bsum;

    for (int j = tid; j < qEnd; j += 256)
        r[j] = (j <= q) ? buf[j] * inv : 0.f;
}

// ---------------------------------------------------------------------------
// kernel_launch
// ---------------------------------------------------------------------------
extern "C" void kernel_launch(void* const* d_in, const int* in_sizes, int n_in,
                              void* d_out, int out_size)
{
    const float* q  = (const float*)d_in[0];
    const float* k  = (const float*)d_in[1];
    const float* v  = (const float*)d_in[2];
    // d_in[3] = causal tril mask (handled analytically)
    const float* wq = (const float*)d_in[4];
    const float* bq = (const float*)d_in[5];
    const float* wk = (const float*)d_in[6];
    const float* bk = (const float*)d_in[7];
    const float* wv = (const float*)d_in[8];
    const float* bv = (const float*)d_in[9];
    const float* wo = (const float*)d_in[10];
    const float* bo = (const float*)d_in[11];
    float* out = (float*)d_out;

    float *qh, *kh, *vh, *ctx, *attn_s;
    cudaGetSymbolAddress((void**)&qh,     g_qh);
    cudaGetSymbolAddress((void**)&kh,     g_kh);
    cudaGetSymbolAddress((void**)&vh,     g_vh);
    cudaGetSymbolAddress((void**)&ctx,    g_ctx);
    cudaGetSymbolAddress((void**)&attn_s, g_attn_scratch);

    const long long OUT_E  = (long long)Bq * Sq * DM;
    const long long ATTN_E = (long long)Bq * Hq * Sq * Sq;
    float* attn = ((long long)out_size >= OUT_E + ATTN_E) ? (out + OUT_E) : attn_s;

    static int attr_done = 0;
    if (!attr_done) {
        cudaFuncSetAttribute(gemm_tc, cudaFuncAttributeMaxDynamicSharedMemorySize, SMEM_BYTES);
        attr_done = 1;
    }

    // 1: fused QKV projections (z selects operand set)
    GemmP pq = {};
    pq.X = q;  pq.W = wq; pq.bias = bq; pq.Y = qh;
    pq.X1 = k; pq.W1 = wk; pq.b1 = bk; pq.Y1 = kh;
    pq.X2 = v; pq.W2 = wv; pq.b2 = bv; pq.Y2 = vh;
    pq.M = Bq * Sq; pq.N = DM; pq.K = DM; pq.ldw = 0;
    pq.scale = 1.f; pq.out_mode = 1; pq.causal_mode = 0; pq.wrow = 0; pq.qkv = 1;
    gemm_tc<<<dim3(DM / 128, (Bq * Sq) / 128, 3), 256, SMEM_BYTES>>>(pq);

    // 2: scores = qh @ kh^T / 8 (causal; skipped tiles zero-filled)
    GemmP ps = {};
    ps.X = qh; ps.W = kh; ps.bias = nullptr; ps.Y = attn;
    ps.M = Sq; ps.N = Sq; ps.K = DHq; ps.ldw = 0;
    ps.sXz = (long long)Sq * DHq; ps.sWz = (long long)Sq * DHq; ps.sYz = (long long)Sq * Sq;
    ps.scale = 0.125f; ps.out_mode = 0; ps.causal_mode = 1; ps.wrow = 0; ps.qkv = 0;
    gemm_tc<<<dim3(Sq / 128, Sq / 128, Bq * Hq), 256, SMEM_BYTES>>>(ps);

    // 3: causal softmax (touches only valid+diag-tile region)
    softmax_k<<<Bq * Hq * Sq, 256>>>(attn);

    // 4: ctx = attn @ vh  (vh consumed as [K,N] row-major via wrow path)
    GemmP pc = {};
    pc.X = attn; pc.W = vh; pc.bias = nullptr; pc.Y = ctx;
    pc.M = Sq; pc.N = DHq; pc.K = Sq; pc.ldw = DHq;
    pc.sXz = (long long)Sq * Sq; pc.sWz = (long long)Sq * DHq; pc.sYz = 0;
    pc.scale = 1.f; pc.out_mode = 3; pc.causal_mode = 2; pc.wrow = 1; pc.qkv = 0;
    gemm_tc<<<dim3(1, Sq / 128, Bq * Hq), 256, SMEM_BYTES>>>(pc);

    // 5: out = ctx @ wo^T + bo
    GemmP po = {};
    po.X = ctx; po.W = wo; po.bias = bo; po.Y = out;
    po.M = Bq * Sq; po.N = DM; po.K = DM; po.ldw = 0;
    po.scale = 1.f; po.out_mode = 0; po.causal_mode = 0; po.wrow = 0; po.qkv = 0;
    gemm_tc<<<dim3(DM / 128, (Bq * Sq) / 128, 1), 256, SMEM_BYTES>>>(po);
}

// round 5
// speedup vs baseline: 2.4641x; 1.0152x over previous
#include <cuda_runtime.h>
#include <math.h>

// Problem constants
#define Bq 2
#define Sq 2048
#define DM 1024
#define Hq 16
#define DHq 64

// ---------------------------------------------------------------------------
// Scratch (__device__ globals; no runtime allocation)
// ---------------------------------------------------------------------------
__device__ float g_qh [(size_t)Bq * Hq * Sq * DHq];   // [B,H,S,DH]
__device__ float g_kh [(size_t)Bq * Hq * Sq * DHq];   // [B,H,S,DH]
__device__ float g_vh [(size_t)Bq * Hq * Sq * DHq];   // [B,H,S,DH]
__device__ float g_ctx[(size_t)Bq * Sq * DM];          // [B,S,DM]

// ---------------------------------------------------------------------------
// Common helpers
// ---------------------------------------------------------------------------
__device__ __forceinline__ unsigned f2tf32(float f) {
    unsigned r; asm("cvt.rna.tf32.f32 %0, %1;" : "=r"(r) : "f"(f)); return r;
}
__device__ __forceinline__ void cpa16(float* dst, const float* src) {
    unsigned d = (unsigned)__cvta_generic_to_shared(dst);
    asm volatile("cp.async.cg.shared.global [%0], [%1], 16;" :: "r"(d), "l"(src));
}
__device__ __forceinline__ void cp_commit() { asm volatile("cp.async.commit_group;"); }
__device__ __forceinline__ void cp_wait1()  { asm volatile("cp.async.wait_group 1;"); }

__device__ __forceinline__ void mma8(float* c, unsigned a0, unsigned a1, unsigned a2,
                                     unsigned a3, unsigned b0, unsigned b1) {
    asm volatile(
        "mma.sync.aligned.m16n8k8.row.col.f32.tf32.tf32.f32 "
        "{%0,%1,%2,%3}, {%4,%5,%6,%7}, {%8,%9}, {%0,%1,%2,%3};"
        : "+f"(c[0]), "+f"(c[1]), "+f"(c[2]), "+f"(c[3])
        : "r"(a0), "r"(a1), "r"(a2), "r"(a3), "r"(b0), "r"(b1));
}

// ---------------------------------------------------------------------------
// Projection GEMM (proven round-4 kernel): Y = X @ W^T + bias
// out_mode 0: Y[m*N+n]; out_mode 1: head layout ((b*H+h)*S+s)*DH+d
// qkv=1: blockIdx.z selects among 3 operand sets.
// ---------------------------------------------------------------------------
struct GemmP {
    const float *X, *W, *bias; float *Y;
    const float *X1, *W1, *b1; float *Y1;
    const float *X2, *W2, *b2; float *Y2;
    int M, N, K;
    int out_mode;
    int qkv;
};

#define AS   36
#define A_WORDS 4608     // 128*36
#define G_SMEM_BYTES (4 * A_WORDS * 4)

__global__ __launch_bounds__(256)
void gemm_tc(GemmP p)
{
    const int m0 = blockIdx.y * 128;
    const int n0 = blockIdx.x * 128;
    const int z  = blockIdx.z;
    const int tid = threadIdx.x, lane = tid & 31, warp = tid >> 5;
    const int wm = warp & 1, wn = warp >> 1;

    const float *X = p.X, *W = p.W, *bias = p.bias; float* Y = p.Y;
    if (p.qkv) {
        if (z == 1) { X = p.X1; W = p.W1; bias = p.b1; Y = p.Y1; }
        else if (z == 2) { X = p.X2; W = p.W2; bias = p.b2; Y = p.Y2; }
    }

    extern __shared__ float sm[];
    float* Abuf[2] = { sm,               sm + A_WORDS     };
    float* Bbuf[2] = { sm + 2 * A_WORDS, sm + 3 * A_WORDS };

    auto loadA = [&](float* As_, int k0) {
        int r0 = tid >> 3, c = (tid & 7) * 4;
#pragma unroll
        for (int it = 0; it < 4; it++) {
            int r = r0 + it * 32;
            cpa16(&As_[r * AS + c], &X[(long long)(m0 + r) * p.K + k0 + c]);
        }
    };
    auto loadB = [&](float* Bs_, int k0) {
        int r0 = tid >> 3, c = (tid & 7) * 4;
#pragma unroll
        for (int it = 0; it < 4; it++) {
            int r = r0 + it * 32;
            cpa16(&Bs_[r * AS + c], &W[(long long)(n0 + r) * p.K + k0 + c]);
        }
    };

    float acc[4][4][4] = {};

    loadA(Abuf[0], 0); loadB(Bbuf[0], 0); cp_commit();
    int st = 0;
    for (int k0 = 0; k0 < p.K; k0 += 32) {
        if (k0 + 32 < p.K) { loadA(Abuf[st ^ 1], k0 + 32); loadB(Bbuf[st ^ 1], k0 + 32); }
        cp_commit();
        cp_wait1();
        __syncthreads();

        const float* As_ = Abuf[st];
        const float* Bs_ = Bbuf[st];
#pragma unroll
        for (int kk = 0; kk < 32; kk += 8) {
            unsigned a[4][4];
#pragma unroll
            for (int i = 0; i < 4; i++) {
                int mr = wm * 64 + i * 16 + (lane >> 2);
                int kc = kk + (lane & 3);
                a[i][0] = f2tf32(As_[mr * AS + kc]);
                a[i][1] = f2tf32(As_[(mr + 8) * AS + kc]);
                a[i][2] = f2tf32(As_[mr * AS + kc + 4]);
                a[i][3] = f2tf32(As_[(mr + 8) * AS + kc + 4]);
            }
            unsigned b[4][2];
#pragma unroll
            for (int j = 0; j < 4; j++) {
                int nr = wn * 32 + j * 8 + (lane >> 2);
                int kc = kk + (lane & 3);
                b[j][0] = f2tf32(Bs_[nr * AS + kc]);
                b[j][1] = f2tf32(Bs_[nr * AS + kc + 4]);
            }
#pragma unroll
            for (int i = 0; i < 4; i++)
#pragma unroll
                for (int j = 0; j < 4; j++)
                    mma8(acc[i][j], a[i][0], a[i][1], a[i][2], a[i][3], b[j][0], b[j][1]);
        }
        __syncthreads();
        st ^= 1;
    }

#pragma unroll
    for (int i = 0; i < 4; i++)
#pragma unroll
        for (int j = 0; j < 4; j++)
#pragma unroll
            for (int h = 0; h < 2; h++) {
                int m = m0 + wm * 64 + i * 16 + (lane >> 2) + h * 8;
                int n = n0 + wn * 32 + j * 8 + (lane & 3) * 2;
                float v0 = acc[i][j][h * 2]     + (bias ? bias[n]     : 0.f);
                float v1 = acc[i][j][h * 2 + 1] + (bias ? bias[n + 1] : 0.f);
                long long idx;
                if (p.out_mode == 0) {
                    idx = (long long)m * p.N + n;
                } else {
                    int b_ = m >> 11;          // /S
                    int s  = m & (Sq - 1);
                    int hh = n >> 6;           // /DH
                    int d  = n & (DHq - 1);
                    idx = (((long long)b_ * Hq + hh) * Sq + s) * DHq + d;
                }
                *(float2*)&Y[idx] = make_float2(v0, v1);
            }
}

// ---------------------------------------------------------------------------
// Fused flash attention.
// Block = one head (z) x 128 query rows (qt). 8 warps, each owns 16 rows.
// Pass A: stream K/V tiles, S=Q@K^T (Q prescaled 1/8), P=exp(S) (max=0),
//         ctx += P@V with A-frags gathered from P registers via quad shuffles,
//         row sums l accumulated. Epilogue: ctx /= l -> g_ctx.
// Pass B (if attn is an output): re-stream K, recompute S, write exp(S)/l,
//         zero-fill the causal upper region.
// smem: Qs[128][68] tf32, Ks[2][128][68] f32, Vs[2][128][72] f32 = 178176 B.
// ---------------------------------------------------------------------------
#define QS_OFF 0
#define KS_OFF 8704            // 128*68
#define VS_OFF (8704 + 2*8704) // 26112
#define F_SMEM_WORDS (26112 + 2*9216)
#define F_SMEM_BYTES (F_SMEM_WORDS * 4)

__global__ __launch_bounds__(256, 1)
void attn_flash(const float* __restrict__ qh, const float* __restrict__ kh,
                const float* __restrict__ vh, float* __restrict__ ctx,
                float* __restrict__ attn, int write_attn)
{
    const int qt = blockIdx.x;          // query tile
    const int z  = blockIdx.y;          // b*H + h
    const int tid = threadIdx.x, lane = tid & 31, warp = tid >> 5;

    extern __shared__ float sm[];
    unsigned* Qs = (unsigned*)(sm + QS_OFF);
    float* Ksb[2] = { sm + KS_OFF, sm + KS_OFF + 8704 };
    float* Vsb[2] = { sm + VS_OFF, sm + VS_OFF + 9216 };

    const float* Qg = qh + ((long long)z * Sq + qt * 128) * DHq;
    const float* Kg = kh + (long long)z * Sq * DHq;
    const float* Vg = vh + (long long)z * Sq * DHq;

    // Q fill: scaled by 1/8, converted to tf32 once
    for (int i = tid; i < 128 * 16; i += 256) {
        int r = i >> 4, c4 = (i & 15) * 4;
        float4 v = *(const float4*)&Qg[r * 64 + c4];
        unsigned* d = &Qs[r * 68 + c4];
        d[0] = f2tf32(v.x * 0.125f); d[1] = f2tf32(v.y * 0.125f);
        d[2] = f2tf32(v.z * 0.125f); d[3] = f2tf32(v.w * 0.125f);
    }

    auto loadK = [&](int kt, int buf) {
        for (int i = tid; i < 128 * 16; i += 256) {
            int r = i >> 4, c4 = (i & 15) * 4;
            cpa16(&Ksb[buf][r * 68 + c4], &Kg[((long long)kt * 128 + r) * 64 + c4]);
        }
    };
    auto loadV = [&](int kt, int buf) {
        for (int i = tid; i < 128 * 16; i += 256) {
            int r = i >> 4, c4 = (i & 15) * 4;
            cpa16(&Vsb[buf][r * 72 + c4], &Vg[((long long)kt * 128 + r) * 64 + c4]);
        }
    };

    const unsigned* Qw = &Qs[(warp * 16) * 68];
    const int rq = lane >> 2;           // row within warp slab (and +8)
    const int rbase = qt * 128 + warp * 16 + rq;

    float cacc[8][4] = {};
    float l0 = 0.f, l1 = 0.f;
    float p[16][4];

    loadK(0, 0); loadV(0, 0); cp_commit();

    for (int kt = 0; kt <= qt; kt++) {
        int buf = kt & 1;
        __syncthreads();                         // prev compute done before overwrite
        if (kt < qt) { loadK(kt + 1, buf ^ 1); loadV(kt + 1, buf ^ 1); }
        cp_commit();
        cp_wait1();
        __syncthreads();

        const float* Kb = Ksb[buf];
        const float* Vb = Vsb[buf];

        // ---- S = Q @ K^T ----
#pragma unroll
        for (int j = 0; j < 16; j++) { p[j][0] = p[j][1] = p[j][2] = p[j][3] = 0.f; }
#pragma unroll
        for (int ks = 0; ks < 8; ks++) {
            int kc = ks * 8 + (lane & 3);
            unsigned a0 = Qw[rq * 68 + kc];
            unsigned a1 = Qw[(rq + 8) * 68 + kc];
            unsigned a2 = Qw[rq * 68 + kc + 4];
            unsigned a3 = Qw[(rq + 8) * 68 + kc + 4];
#pragma unroll
            for (int j = 0; j < 16; j++) {
                int n = j * 8 + rq;
                unsigned b0 = f2tf32(Kb[n * 68 + kc]);
                unsigned b1 = f2tf32(Kb[n * 68 + kc + 4]);
                mma8(p[j], a0, a1, a2, a3, b0, b1);
            }
        }

        // ---- mask + exp + row-sum ----
        bool diag = (kt == qt);
#pragma unroll
        for (int j = 0; j < 16; j++) {
            int c0 = kt * 128 + j * 8 + 2 * (lane & 3);
            float e0 = (!diag || c0     <= rbase    ) ? __expf(p[j][0]) : 0.f;
            float e1 = (!diag || c0 + 1 <= rbase    ) ? __expf(p[j][1]) : 0.f;
            float e2 = (!diag || c0     <= rbase + 8) ? __expf(p[j][2]) : 0.f;
            float e3 = (!diag || c0 + 1 <= rbase + 8) ? __expf(p[j][3]) : 0.f;
            p[j][0] = e0; p[j][1] = e1; p[j][2] = e2; p[j][3] = e3;
            l0 += e0 + e1; l1 += e2 + e3;
        }

        // ---- ctx += P @ V  (A-frags gathered from P regs via quad shuffles) ----
#pragma unroll
        for (int ks2 = 0; ks2 < 16; ks2++) {
            int hlo = (lane & ~3) | ((lane & 3) >> 1);
            int hhi = hlo | 2;
            float v00 = __shfl_sync(0xffffffffu, p[ks2][0], hlo);
            float v01 = __shfl_sync(0xffffffffu, p[ks2][1], hlo);
            float v20 = __shfl_sync(0xffffffffu, p[ks2][2], hlo);
            float v21 = __shfl_sync(0xffffffffu, p[ks2][3], hlo);
            float w00 = __shfl_sync(0xffffffffu, p[ks2][0], hhi);
            float w01 = __shfl_sync(0xffffffffu, p[ks2][1], hhi);
            float w20 = __shfl_sync(0xffffffffu, p[ks2][2], hhi);
            float w21 = __shfl_sync(0xffffffffu, p[ks2][3], hhi);
            bool odd = lane & 1;
            unsigned a0 = f2tf32(odd ? v01 : v00);
            unsigned a1 = f2tf32(odd ? v21 : v20);
            unsigned a2 = f2tf32(odd ? w01 : w00);
            unsigned a3 = f2tf32(odd ? w21 : w20);
            int kr = ks2 * 8 + (lane & 3);
#pragma unroll
            for (int j = 0; j < 8; j++) {
                int n = j * 8 + rq;
                unsigned b0 = f2tf32(Vb[kr * 72 + n]);
                unsigned b1 = f2tf32(Vb[(kr + 4) * 72 + n]);
                mma8(cacc[j], a0, a1, a2, a3, b0, b1);
            }
        }
    }

    // ---- finalize l (rows live entirely within the warp) ----
    l0 += __shfl_xor_sync(0xffffffffu, l0, 1);
    l0 += __shfl_xor_sync(0xffffffffu, l0, 2);
    l1 += __shfl_xor_sync(0xffffffffu, l1, 1);
    l1 += __shfl_xor_sync(0xffffffffu, l1, 2);
    float inv0 = 1.0f / l0, inv1 = 1.0f / l1;

    // ---- ctx epilogue -> g_ctx [b][s][h*64+d] ----
    {
        int b_ = z >> 4, h_ = z & 15;
        long long base0 = ((long long)b_ * Sq + rbase) * DM + h_ * 64;
        long long base1 = base0 + 8LL * DM;
#pragma unroll
        for (int j = 0; j < 8; j++) {
            int d = j * 8 + 2 * (lane & 3);
            *(float2*)&ctx[base0 + d] = make_float2(cacc[j][0] * inv0, cacc[j][1] * inv0);
            *(float2*)&ctx[base1 + d] = make_float2(cacc[j][2] * inv1, cacc[j][3] * inv1);
        }
    }

    // ---- Pass B: write normalized attn (only if it's part of the output) ----
    if (write_attn) {
        float* A = attn + (long long)z * Sq * Sq;
        __syncthreads();
        loadK(0, 0); cp_commit();
        for (int kt = 0; kt <= qt; kt++) {
            int buf = kt & 1;
            __syncthreads();
            if (kt < qt) loadK(kt + 1, buf ^ 1);
            cp_commit();
            cp_wait1();
            __syncthreads();

            const float* Kb = Ksb[buf];
#pragma unroll
            for (int j = 0; j < 16; j++) { p[j][0] = p[j][1] = p[j][2] = p[j][3] = 0.f; }
#pragma unroll
            for (int ks = 0; ks < 8; ks++) {
                int kc = ks * 8 + (lane & 3);
                unsigned a0 = Qw[rq * 68 + kc];
                unsigned a1 = Qw[(rq + 8) * 68 + kc];
                unsigned a2 = Qw[rq * 68 + kc + 4];
                unsigned a3 = Qw[(rq + 8) * 68 + kc + 4];
#pragma unroll
                for (int j = 0; j < 16; j++) {
                    int n = j * 8 + rq;
                    unsigned b0 = f2tf32(Kb[n * 68 + kc]);
                    unsigned b1 = f2tf32(Kb[n * 68 + kc + 4]);
                    mma8(p[j], a0, a1, a2, a3, b0, b1);
                }
            }
            bool diag = (kt == qt);
            long long row0 = (long long)rbase * Sq;
            long long row1 = (long long)(rbase + 8) * Sq;
#pragma unroll
            for (int j = 0; j < 16; j++) {
                int c0 = kt * 128 + j * 8 + 2 * (lane & 3);
                float e0 = (!diag || c0     <= rbase    ) ? __expf(p[j][0]) * inv0 : 0.f;
                float e1 = (!diag || c0 + 1 <= rbase    ) ? __expf(p[j][1]) * inv0 : 0.f;
                float e2 = (!diag || c0     <= rbase + 8) ? __expf(p[j][2]) * inv1 : 0.f;
                float e3 = (!diag || c0 + 1 <= rbase + 8) ? __expf(p[j][3]) * inv1 : 0.f;
                *(float2*)&A[row0 + c0] = make_float2(e0, e1);
                *(float2*)&A[row1 + c0] = make_float2(e2, e3);
            }
        }
        // zero-fill the strictly-causal-upper region (d_out is poisoned)
        int cEnd = (qt + 1) * 128;
        int nz4 = (Sq - cEnd) >> 2;
        if (nz4 > 0) {
            float4 z4 = make_float4(0.f, 0.f, 0.f, 0.f);
            for (int i = tid; i < 128 * nz4; i += 256) {
                int r = i / nz4, c = (i - r * nz4) * 4;
                *(float4*)&A[(long long)(qt * 128 + r) * Sq + cEnd + c] = z4;
            }
        }
    }
}

// ---------------------------------------------------------------------------
// kernel_launch
// ---------------------------------------------------------------------------
extern "C" void kernel_launch(void* const* d_in, const int* in_sizes, int n_in,
                              void* d_out, int out_size)
{
    const float* q  = (const float*)d_in[0];
    const float* k  = (const float*)d_in[1];
    const float* v  = (const float*)d_in[2];
    // d_in[3] = causal tril mask (handled analytically)
    const float* wq = (const float*)d_in[4];
    const float* bq = (const float*)d_in[5];
    const float* wk = (const float*)d_in[6];
    const float* bk = (const float*)d_in[7];
    const float* wv = (const float*)d_in[8];
    const float* bv = (const float*)d_in[9];
    const float* wo = (const float*)d_in[10];
    const float* bo = (const float*)d_in[11];
    float* out = (float*)d_out;

    float *qh, *kh, *vh, *ctx;
    cudaGetSymbolAddress((void**)&qh,  g_qh);
    cudaGetSymbolAddress((void**)&kh,  g_kh);
    cudaGetSymbolAddress((void**)&vh,  g_vh);
    cudaGetSymbolAddress((void**)&ctx, g_ctx);

    const long long OUT_E  = (long long)Bq * Sq * DM;
    const long long ATTN_E = (long long)Bq * Hq * Sq * Sq;
    int write_attn = ((long long)out_size >= OUT_E + ATTN_E) ? 1 : 0;
    float* attn = out + OUT_E;   // only dereferenced when write_attn

    static int attr_done = 0;
    if (!attr_done) {
        cudaFuncSetAttribute(gemm_tc, cudaFuncAttributeMaxDynamicSharedMemorySize, G_SMEM_BYTES);
        cudaFuncSetAttribute(attn_flash, cudaFuncAttributeMaxDynamicSharedMemorySize, F_SMEM_BYTES);
        attr_done = 1;
    }

    // 1: fused QKV projections (z selects operand set) -> head layouts
    GemmP pq = {};
    pq.X = q;  pq.W = wq; pq.bias = bq; pq.Y = qh;
    pq.X1 = k; pq.W1 = wk; pq.b1 = bk; pq.Y1 = kh;
    pq.X2 = v; pq.W2 = wv; pq.b2 = bv; pq.Y2 = vh;
    pq.M = Bq * Sq; pq.N = DM; pq.K = DM; pq.out_mode = 1; pq.qkv = 1;
    gemm_tc<<<dim3(DM / 128, (Bq * Sq) / 128, 3), 256, G_SMEM_BYTES>>>(pq);

    // 2: fused flash attention (scores + softmax + ctx [+ attn output])
    attn_flash<<<dim3(Sq / 128, Bq * Hq, 1), 256, F_SMEM_BYTES>>>(
        qh, kh, vh, ctx, attn, write_attn);

    // 3: out = ctx @ wo^T + bo
    GemmP po = {};
    po.X = ctx; po.W = wo; po.bias = bo; po.Y = out;
    po.M = Bq * Sq; po.N = DM; po.K = DM; po.out_mode = 0; po.qkv = 0;
    gemm_tc<<<dim3(DM / 128, (Bq * Sq) / 128, 1), 256, G_SMEM_BYTES>>>(po);
}